// round 6
// baseline (speedup 1.0000x reference)
#include <cuda_runtime.h>
#include <cstdint>

#define NQ      8192
#define NR      16384
#define KNN     8
#define NCHUNK  4
#define RPC     (NR / NCHUNK)    // 4096 refs per chunk
#define PPC     (RPC / 2)        // 2048 packed pairs per chunk
#define QPB     64
#define QBLK    (NQ / QPB)       // 128
#define NSL     32               // slices per chunk (x2 packed halves = 64 sub-minima)
#define PPSL    (PPC / NSL)      // 64 pairs per slice
#define CAP     64               // candidate cap per (query, chunk); E[count] ~ 9

typedef unsigned long long ull;

__device__ ulonglong4 g_refp[NR / 2];                       // packed {x01,y01,z01,w01}
__device__ ull        g_ckey[(size_t)NQ * NCHUNK * CAP];    // candidate keys
__device__ int        g_cnt[NQ * NCHUNK];

__device__ __forceinline__ ull fma2(ull a, ull b, ull c) {
    ull d; asm("fma.rn.f32x2 %0, %1, %2, %3;" : "=l"(d) : "l"(a), "l"(b), "l"(c));
    return d;
}
__device__ __forceinline__ ull pk2(float lo, float hi) {
    ull r; asm("mov.b64 %0, {%1, %2};" : "=l"(r) : "f"(lo), "f"(hi));
    return r;
}
__device__ __forceinline__ void up2(float& lo, float& hi, ull v) {
    asm("mov.b64 {%0, %1}, %2;" : "=f"(lo), "=f"(hi) : "l"(v));
}
__device__ __forceinline__ unsigned f2ord(float f) {
    unsigned b = __float_as_uint(f);
    return (b & 0x80000000u) ? ~b : (b | 0x80000000u);
}

// Kernel A: pack reference pairs into {x01,y01,z01,w01} (w = r^2, reference rounding).
__global__ void knn_pack(const float* __restrict__ ref) {
    int p = blockIdx.x * blockDim.x + threadIdx.x;
    if (p >= NR / 2) return;
    const float* a = ref + (size_t)p * 6;
    float x0 = a[0], y0 = a[1], z0 = a[2], x1 = a[3], y1 = a[4], z1 = a[5];
    float w0 = __fadd_rn(__fadd_rn(__fmul_rn(x0, x0), __fmul_rn(y0, y0)), __fmul_rn(z0, z0));
    float w1 = __fadd_rn(__fadd_rn(__fmul_rn(x1, x1), __fmul_rn(y1, y1)), __fmul_rn(z1, z1));
    ulonglong4 v;
    v.x = pk2(x0, x1); v.y = pk2(y0, y1); v.z = pk2(z0, z1); v.w = pk2(w0, w1);
    g_refp[p] = v;
}

// Kernel B: per (query, chunk): branchless sub-minima pass -> tau, then
// compaction pass collecting all s <= tau. No atomics; deterministic.
__global__ __launch_bounds__(QPB) void knn_p1(const float* __restrict__ qry) {
    const int chunk = blockIdx.x % NCHUNK;     // 148 % 4 == 0 -> chunk/SM affinity
    const int qi    = (blockIdx.x / NCHUNK) * QPB + threadIdx.x;
    const int pbase = chunk * PPC;

    const float qx = qry[qi * 3 + 0];
    const float qy = qry[qi * 3 + 1];
    const float qz = qry[qi * 3 + 2];
    const ull m2x = pk2(-2.0f * qx, -2.0f * qx);
    const ull m2y = pk2(-2.0f * qy, -2.0f * qy);
    const ull m2z = pk2(-2.0f * qz, -2.0f * qz);

    const float INF = __int_as_float(0x7f800000);

    // Pass A: 64 sub-slice minima (branchless), folded into a sorted-8 of values.
    float t[KNN];
#pragma unroll
    for (int j = 0; j < KNN; ++j) t[j] = INF;

    for (int sl = 0; sl < NSL; ++sl) {
        float a0 = INF, a1 = INF;
        const ulonglong4* base = g_refp + pbase + sl * PPSL;
#pragma unroll 8
        for (int it = 0; it < PPSL; ++it) {
            ulonglong4 v = base[it];
            ull s2 = fma2(m2x, v.x, fma2(m2y, v.y, fma2(m2z, v.z, v.w)));
            float s0, s1; up2(s0, s1, s2);
            a0 = fminf(a0, s0); a1 = fminf(a1, s1);
        }
        float c0 = a0;
#pragma unroll
        for (int j = 0; j < KNN; ++j) { float lo = fminf(t[j], c0), hi = fmaxf(t[j], c0); t[j] = lo; c0 = hi; }
        float c1 = a1;
#pragma unroll
        for (int j = 0; j < KNN; ++j) { float lo = fminf(t[j], c1), hi = fmaxf(t[j], c1); t[j] = lo; c1 = hi; }
    }
    // tau = 8th smallest of 64 sub-minima >= chunk's true 8th smallest distance.
    const float tau = t[KNN - 1];

    // Pass C: compact candidate keys (ord(s)<<32 | idx) for s <= tau.
    int c = 0;
    ull* buf = g_ckey + ((size_t)qi * NCHUNK + chunk) * CAP;
#pragma unroll 4
    for (int p = 0; p < PPC; ++p) {
        ulonglong4 v = g_refp[pbase + p];
        ull s2 = fma2(m2x, v.x, fma2(m2y, v.y, fma2(m2z, v.z, v.w)));
        float s0, s1; up2(s0, s1, s2);
        bool h0 = (s0 <= tau), h1 = (s1 <= tau);
        if (__any_sync(0xffffffffu, h0 | h1)) {
            int ri = (pbase + p) * 2;
            if (h0) { buf[c < CAP ? c : CAP - 1] = ((ull)f2ord(s0) << 32) | (unsigned)ri;       ++c; }
            if (h1) { buf[c < CAP ? c : CAP - 1] = ((ull)f2ord(s1) << 32) | (unsigned)(ri + 1); ++c; }
        }
    }
    g_cnt[qi * NCHUNK + chunk] = (c < CAP) ? c : CAP;
}

// Kernel C: merge candidates per query (~36 keys), emit top-8 indices as floats.
__global__ void knn_p2(float* __restrict__ out) {
    int qi = blockIdx.x * blockDim.x + threadIdx.x;
    if (qi >= NQ) return;

    ull best[KNN];
#pragma unroll
    for (int j = 0; j < KNN; ++j) best[j] = ~0ull;

    for (int ch = 0; ch < NCHUNK; ++ch) {
        int n = g_cnt[qi * NCHUNK + ch];
        const ull* buf = g_ckey + ((size_t)qi * NCHUNK + ch) * CAP;
        for (int j = 0; j < n; ++j) {
            ull k = buf[j];
            if (k < best[KNN - 1]) {
#pragma unroll
                for (int m = 0; m < KNN; ++m) {
                    if (k < best[m]) { ull tmp = best[m]; best[m] = k; k = tmp; }
                }
            }
        }
    }
#pragma unroll
    for (int j = 0; j < KNN; ++j)
        out[qi * KNN + j] = (float)(int)(best[j] & 0xffffffffu);
}

extern "C" void kernel_launch(void* const* d_in, const int* in_sizes, int n_in,
                              void* d_out, int out_size) {
    (void)n_in; (void)out_size;
    const float* q;
    const float* r;
    if (in_sizes[0] < in_sizes[1]) { q = (const float*)d_in[0]; r = (const float*)d_in[1]; }
    else                           { q = (const float*)d_in[1]; r = (const float*)d_in[0]; }

    knn_pack<<<(NR / 2 + 255) / 256, 256>>>(r);
    knn_p1<<<QBLK * NCHUNK, QPB>>>(q);
    knn_p2<<<(NQ + 255) / 256, 256>>>((float*)d_out);
}

// round 7
// speedup vs baseline: 3.7912x; 3.7912x over previous
#include <cuda_runtime.h>
#include <cstdint>

#define NQ      8192
#define NR      16384
#define KNN     8
#define NCHUNK  16
#define RPC     (NR / NCHUNK)    // 1024 refs per chunk
#define PPC     (RPC / 2)        // 512 packed pairs per chunk (16 KB tile)
#define QPB     256              // threads (=queries) per block, 8 warps
#define QBLK    (NQ / QPB)       // 32 query-blocks
#define NSL     16               // slices per chunk
#define PPSL    (PPC / NSL)      // 32 pairs per slice -> 32 sub-minima (2/slice)
#define CAP     32               // candidate cap per (query, chunk); E ~ 13

typedef unsigned long long ull;

__device__ ulonglong4 g_refp[NR / 2];                       // packed {x01,y01,z01,w01}
__device__ ull        g_ckey[(size_t)NQ * NCHUNK * CAP];    // 32 MB candidate keys
__device__ int        g_cnt[NQ * NCHUNK];

__device__ __forceinline__ ull fma2(ull a, ull b, ull c) {
    ull d; asm("fma.rn.f32x2 %0, %1, %2, %3;" : "=l"(d) : "l"(a), "l"(b), "l"(c));
    return d;
}
__device__ __forceinline__ ull pk2(float lo, float hi) {
    ull r; asm("mov.b64 %0, {%1, %2};" : "=l"(r) : "f"(lo), "f"(hi));
    return r;
}
__device__ __forceinline__ void up2(float& lo, float& hi, ull v) {
    asm("mov.b64 {%0, %1}, %2;" : "=f"(lo), "=f"(hi) : "l"(v));
}
__device__ __forceinline__ unsigned f2ord(float f) {
    unsigned b = __float_as_uint(f);
    return (b & 0x80000000u) ? ~b : (b | 0x80000000u);
}

// Kernel A: pack reference pairs into {x01,y01,z01,w01}, w = r^2 (reference rounding).
__global__ void knn_pack(const float* __restrict__ ref) {
    int p = blockIdx.x * blockDim.x + threadIdx.x;
    if (p >= NR / 2) return;
    const float* a = ref + (size_t)p * 6;
    float x0 = a[0], y0 = a[1], z0 = a[2], x1 = a[3], y1 = a[4], z1 = a[5];
    float w0 = __fadd_rn(__fadd_rn(__fmul_rn(x0, x0), __fmul_rn(y0, y0)), __fmul_rn(z0, z0));
    float w1 = __fadd_rn(__fadd_rn(__fmul_rn(x1, x1), __fmul_rn(y1, y1)), __fmul_rn(z1, z1));
    ulonglong4 v;
    v.x = pk2(x0, x1); v.y = pk2(y0, y1); v.z = pk2(z0, z1); v.w = pk2(w0, w1);
    g_refp[p] = v;
}

// Kernel B: block stages its chunk in SMEM once; all 8 warps run both passes
// from LDS (broadcast, conflict-free). Zero-event pass A -> tau, then rare-event
// candidate compaction. No atomics; deterministic.
__global__ __launch_bounds__(QPB) void knn_p1(const float* __restrict__ qry) {
    __shared__ ulonglong4 tile[PPC];          // 16 KB
    const int chunk = blockIdx.x % NCHUNK;
    const int qi    = (blockIdx.x / NCHUNK) * QPB + threadIdx.x;
    const int rbase = chunk * RPC;

    // Cooperative tile fill (coalesced LDG.128 x2 per pair).
    for (int p = threadIdx.x; p < PPC; p += QPB)
        tile[p] = g_refp[chunk * PPC + p];

    const float qx = qry[qi * 3 + 0];
    const float qy = qry[qi * 3 + 1];
    const float qz = qry[qi * 3 + 2];
    const ull m2x = pk2(-2.0f * qx, -2.0f * qx);
    const ull m2y = pk2(-2.0f * qy, -2.0f * qy);
    const ull m2z = pk2(-2.0f * qz, -2.0f * qz);

    const float INF = __int_as_float(0x7f800000);
    __syncthreads();

    // Pass A (branchless): 32 sub-minima (2 packed halves x 16 slices),
    // folded into a sorted-8 of values via fmin/fmax chains.
    float t[KNN];
#pragma unroll
    for (int j = 0; j < KNN; ++j) t[j] = INF;

    for (int sl = 0; sl < NSL; ++sl) {
        float a0 = INF, a1 = INF;
        const ulonglong4* base = tile + sl * PPSL;
#pragma unroll 8
        for (int it = 0; it < PPSL; ++it) {
            ulonglong4 v = base[it];          // warp-uniform -> LDS broadcast
            ull s2 = fma2(m2x, v.x, fma2(m2y, v.y, fma2(m2z, v.z, v.w)));
            float s0, s1; up2(s0, s1, s2);
            a0 = fminf(a0, s0); a1 = fminf(a1, s1);
        }
        float c0 = a0;
#pragma unroll
        for (int j = 0; j < KNN; ++j) { float lo = fminf(t[j], c0), hi = fmaxf(t[j], c0); t[j] = lo; c0 = hi; }
        float c1 = a1;
#pragma unroll
        for (int j = 0; j < KNN; ++j) { float lo = fminf(t[j], c1), hi = fmaxf(t[j], c1); t[j] = lo; c1 = hi; }
    }
    // tau >= chunk's true 8th-smallest distance (8 distinct elements <= tau exist).
    const float tau = t[KNN - 1];

    // Pass C: compact keys (ord(s)<<32 | idx) for s <= tau. Bit-identical recompute.
    int c = 0;
    ull* buf = g_ckey + ((size_t)qi * NCHUNK + chunk) * CAP;
#pragma unroll 4
    for (int p = 0; p < PPC; ++p) {
        ulonglong4 v = tile[p];
        ull s2 = fma2(m2x, v.x, fma2(m2y, v.y, fma2(m2z, v.z, v.w)));
        float s0, s1; up2(s0, s1, s2);
        bool h0 = (s0 <= tau), h1 = (s1 <= tau);
        if (__any_sync(0xffffffffu, h0 | h1)) {
            int ri = rbase + p * 2;
            if (h0) { buf[c < CAP ? c : CAP - 1] = ((ull)f2ord(s0) << 32) | (unsigned)ri;       ++c; }
            if (h1) { buf[c < CAP ? c : CAP - 1] = ((ull)f2ord(s1) << 32) | (unsigned)(ri + 1); ++c; }
        }
    }
    g_cnt[qi * NCHUNK + chunk] = (c < CAP) ? c : CAP;
}

// Kernel C: merge ~13x16 candidates per query; emit top-8 indices as floats.
__global__ void knn_p2(float* __restrict__ out) {
    int qi = blockIdx.x * blockDim.x + threadIdx.x;
    if (qi >= NQ) return;

    ull best[KNN];
#pragma unroll
    for (int j = 0; j < KNN; ++j) best[j] = ~0ull;

    for (int ch = 0; ch < NCHUNK; ++ch) {
        int n = g_cnt[qi * NCHUNK + ch];
        const ull* buf = g_ckey + ((size_t)qi * NCHUNK + ch) * CAP;
        for (int j = 0; j < n; ++j) {
            ull k = buf[j];
            if (k < best[KNN - 1]) {
#pragma unroll
                for (int m = 0; m < KNN; ++m) {
                    if (k < best[m]) { ull tmp = best[m]; best[m] = k; k = tmp; }
                }
            }
        }
    }
#pragma unroll
    for (int j = 0; j < KNN; ++j)
        out[qi * KNN + j] = (float)(int)(best[j] & 0xffffffffu);
}

extern "C" void kernel_launch(void* const* d_in, const int* in_sizes, int n_in,
                              void* d_out, int out_size) {
    (void)n_in; (void)out_size;
    const float* q;
    const float* r;
    if (in_sizes[0] < in_sizes[1]) { q = (const float*)d_in[0]; r = (const float*)d_in[1]; }
    else                           { q = (const float*)d_in[1]; r = (const float*)d_in[0]; }

    knn_pack<<<(NR / 2 + 255) / 256, 256>>>(r);
    knn_p1<<<QBLK * NCHUNK, QPB>>>(q);
    knn_p2<<<(NQ + 255) / 256, 256>>>((float*)d_out);
}